// round 14
// baseline (speedup 1.0000x reference)
#include <cuda_runtime.h>
#include <cuda_fp16.h>
#include <mma.h>
#include <cstdint>

using namespace nvcuda;

#define B_  8
#define S_  1024
#define D_  128
#define H_  8
#define HD_ 1024

// Scratch (device globals: allocation-free rule)
__device__ __half g_x[3][B_*S_*D_];      // query+pos, key+pos, value+pos (half)
__device__ __half g_W[3][D_*HD_];        // Wq, Wk, Wv (half)
__device__ __half g_Wo[HD_*D_];          // Wo (half)
__device__ __half g_q[B_*H_*S_*D_];      // (b,h,s,d)
__device__ __half g_k[B_*H_*S_*D_];      // (b,h,s,d)
__device__ __half g_vt[B_*H_*D_*S_];     // (b,h,d,s)  V TRANSPOSED
__device__ __half g_att[B_*S_*HD_];      // (b,s,h*D+d)

__device__ __forceinline__ uint32_t pack_h2(float lo, float hi) {
    uint32_t u;
    asm("cvt.rn.f16x2.f32 %0, %2, %1;" : "=r"(u) : "f"(lo), "f"(hi));
    return u;
}

#define MMA_F16(c, a0, a1, a2, a3, b0, b1) \
    asm volatile("mma.sync.aligned.m16n8k16.row.col.f32.f16.f16.f32 " \
        "{%0,%1,%2,%3}, {%4,%5,%6,%7}, {%8,%9}, {%0,%1,%2,%3};" \
        : "+f"((c)[0]), "+f"((c)[1]), "+f"((c)[2]), "+f"((c)[3]) \
        : "r"(a0), "r"(a1), "r"(a2), "r"(a3), "r"(b0), "r"(b1))

#define LDSM_X4(r0, r1, r2, r3, addr) \
    asm volatile("ldmatrix.sync.aligned.m8n8.x4.shared.b16 {%0,%1,%2,%3}, [%4];" \
        : "=r"(r0), "=r"(r1), "=r"(r2), "=r"(r3) : "r"(addr))

#define CP16(smem_u32, gptr) \
    asm volatile("cp.async.cg.shared.global [%0], [%1], 16;" :: "r"(smem_u32), "l"(gptr))
#define CP_COMMIT() asm volatile("cp.async.commit_group;")
#define CP_WAIT(n)  asm volatile("cp.async.wait_group %0;" :: "n"(n))

// ---------------------------------------------------------------------------
// Prep (merged): z = 0..2.  All blocks: x[z] = half(in[z] + pos).
// Blocks 0-127 additionally convert W[z]; z==2 blocks 128-255 convert Wo.
// ---------------------------------------------------------------------------
__global__ __launch_bounds__(256) void prep_kernel(
    const float* __restrict__ query, const float* __restrict__ key,
    const float* __restrict__ value, const float* __restrict__ pos,
    const float* __restrict__ Wq, const float* __restrict__ Wk,
    const float* __restrict__ Wv, const float* __restrict__ Wo)
{
    const int z = blockIdx.z;
    const float* in = (z == 0) ? query : (z == 1 ? key : value);
    int idx = (blockIdx.x*256 + threadIdx.x)*4;
    {
        float4 a = *reinterpret_cast<const float4*>(in + idx);
        float4 p = *reinterpret_cast<const float4*>(pos + idx);
        uint2 o;
        o.x = pack_h2(a.x+p.x, a.y+p.y);
        o.y = pack_h2(a.z+p.z, a.w+p.w);
        *reinterpret_cast<uint2*>(&g_x[z][idx]) = o;
    }
    if (blockIdx.x < 128) {
        const float* W = (z == 0) ? Wq : (z == 1 ? Wk : Wv);
        float4 a = *reinterpret_cast<const float4*>(W + idx);
        uint2 o;
        o.x = pack_h2(a.x, a.y);
        o.y = pack_h2(a.z, a.w);
        *reinterpret_cast<uint2*>(&g_W[z][idx]) = o;
    } else if (z == 2 && blockIdx.x < 256) {
        int widx = idx - 128*256*4;
        float4 a = *reinterpret_cast<const float4*>(Wo + widx);
        uint2 o;
        o.x = pack_h2(a.x, a.y);
        o.y = pack_h2(a.z, a.w);
        *reinterpret_cast<uint2*>(&g_Wo[widx]) = o;
    }
}

// ---------------------------------------------------------------------------
// Kernel 1: projection GEMM (half).  out = x[z](8192x128) @ W[z](128x1024)+bias
// CTA 128x128 tile, pipelined B loads. q/k -> (b,h,s,d); v -> (b,h,d,s).
// ---------------------------------------------------------------------------
#define PROJ_A_H    (128*136)                 // 17408 halves
#define PROJ_B_H    (64*136)                  // 8704 halves
#define PROJ_STG_F  (64*36)                   // fp32 staging floats per warp
#define PROJ_SMEM_B 73728

__global__ __launch_bounds__(256) void proj_kernel(
    const float* __restrict__ bq, const float* __restrict__ bk,
    const float* __restrict__ bv)
{
    extern __shared__ __half smh[];
    __half* As = smh;
    __half* Bs[2] = { smh + PROJ_A_H, smh + PROJ_A_H + PROJ_B_H };

    const int which = blockIdx.z;
    const float* bias = (which == 0) ? bq : (which == 1 ? bk : bv);

    const int M0 = blockIdx.y * 128;
    const int N0 = blockIdx.x * 128;
    const int tid = threadIdx.x;
    const int wid = tid >> 5, lane = tid & 31;
    const int warp_m = wid >> 2, warp_n = wid & 3;

    const uint32_t da = (uint32_t)__cvta_generic_to_shared(As);
    const __half* Ag = g_x[which] + (size_t)M0*D_;
    const __half* Bg = g_W[which] + N0;

    // group0: full A (128x128) + B chunk 0 (rows 0-63)
    #pragma unroll
    for (int i = 0; i < 8; i++) {
        int idx = tid + i*256;
        int r = idx >> 4, c = idx & 15;
        CP16(da + (uint32_t)(r*136 + c*8)*2u, Ag + (size_t)r*D_ + c*8);
    }
    {
        uint32_t db = (uint32_t)__cvta_generic_to_shared(Bs[0]);
        #pragma unroll
        for (int i = 0; i < 4; i++) {
            int idx = tid + i*256;
            int r = idx >> 4, c = idx & 15;
            CP16(db + (uint32_t)(r*136 + c*8)*2u, Bg + (size_t)r*HD_ + c*8);
        }
    }
    CP_COMMIT();
    // group1: B chunk 1 (rows 64-127)
    {
        uint32_t db = (uint32_t)__cvta_generic_to_shared(Bs[1]);
        #pragma unroll
        for (int i = 0; i < 4; i++) {
            int idx = tid + i*256;
            int r = idx >> 4, c = idx & 15;
            CP16(db + (uint32_t)(r*136 + c*8)*2u, Bg + (size_t)(64 + r)*HD_ + c*8);
        }
    }
    CP_COMMIT();

    wmma::fragment<wmma::accumulator,16,16,16,float> acc[4][2];
    #pragma unroll
    for (int im = 0; im < 4; im++)
        #pragma unroll
        for (int jn = 0; jn < 2; jn++)
            wmma::fill_fragment(acc[im][jn], 0.f);

    #pragma unroll
    for (int ch = 0; ch < 2; ch++) {
        if (ch == 0) CP_WAIT(1); else CP_WAIT(0);
        __syncthreads();
        const __half* Bsk = Bs[ch];
        #pragma unroll
        for (int kk = 0; kk < 4; kk++) {
            wmma::fragment<wmma::matrix_a,16,16,16,__half,wmma::row_major> af[4];
            wmma::fragment<wmma::matrix_b,16,16,16,__half,wmma::row_major> bf[2];
            #pragma unroll
            for (int im = 0; im < 4; im++)
                wmma::load_matrix_sync(af[im],
                    As + (warp_m*64 + im*16)*136 + ch*64 + kk*16, 136);
            #pragma unroll
            for (int jn = 0; jn < 2; jn++)
                wmma::load_matrix_sync(bf[jn], Bsk + (kk*16)*136 + warp_n*32 + jn*16, 136);
            #pragma unroll
            for (int im = 0; im < 4; im++)
                #pragma unroll
                for (int jn = 0; jn < 2; jn++)
                    wmma::mma_sync(acc[im][jn], af[im], bf[jn], acc[im][jn]);
        }
    }
    __syncthreads();   // smem free for fp32 staging

    float* stg = reinterpret_cast<float*>(smh) + wid*PROJ_STG_F;
    #pragma unroll
    for (int im = 0; im < 4; im++)
        #pragma unroll
        for (int jn = 0; jn < 2; jn++)
            wmma::store_matrix_sync(stg + (im*16)*36 + jn*16, acc[im][jn], 36,
                                    wmma::mem_row_major);
    __syncwarp();

    const int b = M0 >> 10;
    const int h = N0 >> 7;

    if (which < 2) {
        __half* outp = (which == 0) ? g_q : g_k;
        #pragma unroll
        for (int it = 0; it < 8; it++) {
            int r = it*8 + (lane >> 2);
            int c0 = (lane & 3)*8;
            int gm = M0 + warp_m*64 + r;
            int s = gm & 1023;
            int d0 = warp_n*32 + c0;
            uint32_t v[4];
            #pragma unroll
            for (int e = 0; e < 4; e++)
                v[e] = pack_h2(stg[r*36 + c0 + 2*e]     + bias[N0 + d0 + 2*e],
                               stg[r*36 + c0 + 2*e + 1] + bias[N0 + d0 + 2*e + 1]);
            *reinterpret_cast<uint4*>(outp + (((size_t)b*H_ + h)*S_ + s)*D_ + d0) =
                *reinterpret_cast<uint4*>(v);
        }
    } else {
        // v: write transposed (b,h,d,s). lane = d-col of warp subtile.
        int d = warp_n*32 + lane;
        float bv_ = bias[N0 + d];
        int s0 = (M0 & 1023) + warp_m*64;
        #pragma unroll
        for (int sp = 0; sp < 8; sp++) {
            uint32_t v[4];
            #pragma unroll
            for (int e = 0; e < 4; e++)
                v[e] = pack_h2(stg[(sp*8 + 2*e)*36 + lane]     + bv_,
                               stg[(sp*8 + 2*e + 1)*36 + lane] + bv_);
            *reinterpret_cast<uint4*>(
                g_vt + (((size_t)b*H_ + h)*D_ + d)*S_ + s0 + sp*8) =
                *reinterpret_cast<uint4*>(v);
        }
    }
}

// ---------------------------------------------------------------------------
// Kernel 2: flash attention (round-11 exact). fp16 mma m16n8k16, single-pass
// softmax (2^-8 offset), ldmatrix.x4 B-frags, K/Vt double-buffered,
// 3 CTAs/SM, l via ones-mma, direct-store epilogue.
// ---------------------------------------------------------------------------
#define ATT_K_H     (64*136)     // 8704 halves
#define ATT_V_H     (128*72)     // 9216 halves
#define ATT_SMEM_B  ((2*ATT_K_H + 2*ATT_V_H)*2 + 256)

__device__ __forceinline__ void cp_ktile(__half* dst, const __half* src, int tid) {
    uint32_t d = (uint32_t)__cvta_generic_to_shared(dst);
    #pragma unroll
    for (int i = 0; i < 8; i++) {
        int idx = tid + i*128;
        int r = idx >> 4, c = idx & 15;
        CP16(d + (uint32_t)(r*136 + c*8)*2u, src + (size_t)r*D_ + c*8);
    }
}
__device__ __forceinline__ void cp_vtile(__half* dst, const __half* src, int tid) {
    uint32_t d = (uint32_t)__cvta_generic_to_shared(dst);
    #pragma unroll
    for (int i = 0; i < 8; i++) {
        int idx = tid + i*128;
        int r = idx >> 3, c = idx & 7;
        CP16(d + (uint32_t)(r*72 + c*8)*2u, src + (size_t)r*S_ + c*8);
    }
}

__global__ __launch_bounds__(128, 3) void attn_kernel(const int* __restrict__ mask)
{
    extern __shared__ __half smh[];
    __half* Ks[2] = { smh, smh + ATT_K_H };
    __half* Vs[2] = { smh + 2*ATT_K_H, smh + 2*ATT_K_H + ATT_V_H };
    float* mbias  = reinterpret_cast<float*>(smh + 2*ATT_K_H + 2*ATT_V_H);

    const int q0 = blockIdx.x * 64;
    const int bh = blockIdx.y;
    const int b  = bh >> 3;
    const int tid = threadIdx.x;
    const int wid = tid >> 5, lane = tid & 31;
    const int g = lane >> 2, t = lane & 3;

    // ldmatrix lane roles
    const int rl   = lane & 7;
    const int msel = (lane >> 3) & 1;
    const int jh   = lane >> 4;

    const uint32_t sbase = (uint32_t)__cvta_generic_to_shared(smh);
    const uint32_t koff = (uint32_t)(((jh*8 + rl)*136 + msel*8)*2);
    const uint32_t voff = (uint32_t)(((jh*8 + rl)*72  + msel*8)*2);

    const __half* Qg = g_q  + ((size_t)bh*S_ + q0)*D_;
    const __half* Kg = g_k  + (size_t)bh*S_*D_;
    const __half* Vg = g_vt + (size_t)bh*D_*S_;

    // G0: K0 -> Ks[0]; G1: Q -> Ks[1] (staging); G2: V0 -> Vs[0]
    cp_ktile(Ks[0], Kg, tid);   CP_COMMIT();
    cp_ktile(Ks[1], Qg, tid);   CP_COMMIT();
    cp_vtile(Vs[0], Vg, tid);   CP_COMMIT();
    CP_WAIT(1);                 // K0, Q landed
    __syncthreads();

    // Q fragments: 8 k16-chunks x 4 regs
    uint32_t qa[8][4];
    {
        const __half* Qw = Ks[1] + (16*wid)*136;
        #pragma unroll
        for (int kc = 0; kc < 8; kc++) {
            qa[kc][0] = *reinterpret_cast<const uint32_t*>(Qw + (g    )*136 + kc*16 + 2*t);
            qa[kc][1] = *reinterpret_cast<const uint32_t*>(Qw + (g + 8)*136 + kc*16 + 2*t);
            qa[kc][2] = *reinterpret_cast<const uint32_t*>(Qw + (g    )*136 + kc*16 + 2*t + 8);
            qa[kc][3] = *reinterpret_cast<const uint32_t*>(Qw + (g + 8)*136 + kc*16 + 2*t + 8);
        }
    }
    __syncthreads();   // all warps read Q -> Ks[1] free

    // G3: K1 -> Ks[1]; G4: V1 -> Vs[1]
    cp_ktile(Ks[1], Kg + 64*D_, tid);  CP_COMMIT();
    cp_vtile(Vs[1], Vg + 64,    tid);  CP_COMMIT();

    float oacc[16][4];
    #pragma unroll
    for (int j = 0; j < 16; j++)
        #pragma unroll
        for (int e = 0; e < 4; e++) oacc[j][e] = 0.f;
    float lacc[4] = {0.f, 0.f, 0.f, 0.f};      // l via ones-mma: c0=row g, c2=row g+8
    const uint32_t ONES = 0x3C003C00u;          // fp16x2 {1.0, 1.0}
    const float scale = 0.08838834764831845f;   // 1/sqrt(128)
    const float EOFF  = 5.545177444479562f;     // 8*ln2: P scaled by 2^-8

    #pragma unroll 1
    for (int kt = 0; kt < 16; kt++) {
        if (tid < 64) mbias[tid] = (mask[b*S_ + kt*64 + tid] ? 0.f : -1e30f) - EOFF;
        CP_WAIT(2);                 // K[kt], V[kt] ready; [kt+1] in flight
        __syncthreads();

        // ---- S = Q K^T : 16 rows x 64 cols per warp (ldmatrix B-frags) ----
        float sacc[8][4];
        #pragma unroll
        for (int j = 0; j < 8; j++)
            #pragma unroll
            for (int e = 0; e < 4; e++) sacc[j][e] = 0.f;

        const uint32_t sKb = sbase + (uint32_t)(kt & 1)*ATT_K_H*2 + koff;
        #pragma unroll
        for (int kc = 0; kc < 8; kc++) {
            #pragma unroll
            for (int q = 0; q < 4; q++) {
                uint32_t b0a, b1a, b0b, b1b;
                LDSM_X4(b0a, b1a, b0b, b1b,
                        sKb + (uint32_t)((q*16*136 + kc*16)*2));
                MMA_F16(sacc[2*q],     qa[kc][0], qa[kc][1], qa[kc][2], qa[kc][3], b0a, b1a);
                MMA_F16(sacc[2*q + 1], qa[kc][0], qa[kc][1], qa[kc][2], qa[kc][3], b0b, b1b);
            }
        }

        // ---- single-pass softmax (2^-8 offset) -> fp16 P frags ----
        uint32_t pa[4][4];
        #pragma unroll
        for (int j = 0; j < 8; j++) {
            float bj0 = mbias[8*j + 2*t], bj1 = mbias[8*j + 2*t + 1];
            float p0 = __expf(fmaf(sacc[j][0], scale, bj0));
            float p1 = __expf(fmaf(sacc[j][1], scale, bj1));
            float p2 = __expf(fmaf(sacc[j][2], scale, bj0));
            float p3 = __expf(fmaf(sacc[j][3], scale, bj1));
            int kc = j >> 1, hi = j & 1;
            pa[kc][0 + 2*hi] = pack_h2(p0, p1);   // row g
            pa[kc][1 + 2*hi] = pack_h2(p2, p3);   // row g+8
        }

        // ---- l += P @ ones (exact fp32 row-sums of rounded P) ----
        #pragma unroll
        for (int kc = 0; kc < 4; kc++)
            MMA_F16(lacc, pa[kc][0], pa[kc][1], pa[kc][2], pa[kc][3], ONES, ONES);

        // ---- O += P V (ldmatrix B-frags from Vt) ----
        const uint32_t sVb = sbase + (uint32_t)(2*ATT_K_H + (kt & 1)*ATT_V_H)*2 + voff;
        #pragma unroll
        for (int kc = 0; kc < 4; kc++) {
            #pragma unroll
            for (int q = 0; q < 8; q++) {
                uint32_t b0a, b1a, b0b, b1b;
                LDSM_X4(b0a, b1a, b0b, b1b,
                        sVb + (uint32_t)((q*16*72 + kc*16)*2));
                MMA_F16(oacc[2*q],     pa[kc][0], pa[kc][1], pa[kc][2], pa[kc][3], b0a, b1a);
                MMA_F16(oacc[2*q + 1], pa[kc][0], pa[kc][1], pa[kc][2], pa[kc][3], b0b, b1b);
            }
        }

        __syncthreads();           // tile reads done -> buffers reusable
        if (kt + 2 < 16) {
            cp_ktile(Ks[kt & 1], Kg + (size_t)(kt+2)*64*D_, tid);
            CP_COMMIT();
            cp_vtile(Vs[kt & 1], Vg + (kt+2)*64, tid);
            CP_COMMIT();
        } else { CP_COMMIT(); CP_COMMIT(); }   // keep group accounting
    }

    // ---- finalize: O/l -> g_att (half), direct stores (round-11) ----
    {
        float inv0 = 1.f / lacc[0], inv8 = 1.f / lacc[2];
        int h = bh & 7;
        int row0 = q0 + 16*wid + g;
        __half* Ob = g_att + ((size_t)(b*S_ + row0))*HD_ + h*D_;
        #pragma unroll
        for (int j = 0; j < 16; j++) {
            int col = 8*j + 2*t;
            *reinterpret_cast<uint32_t*>(Ob + col) =
                pack_h2(oacc[j][0]*inv0, oacc[j][1]*inv0);
            *reinterpret_cast<uint32_t*>(Ob + (size_t)8*HD_ + col) =
                pack_h2(oacc[j][2]*inv8, oacc[j][3]*inv8);
        }
    }
}

// ---------------------------------------------------------------------------
// Kernel 3: output projection. CTA 32x128, K-chunk 128 (8 iters), double-
// buffered cp.async: one full iteration of mma in flight covers the L2
// latency chain; barrier/wait count per unit work halved vs 64-chunks.
// ---------------------------------------------------------------------------
#define OP_A_H    (32*136)    // 4352 halves
#define OP_B_H    (128*136)   // 17408 halves
#define OP_SMEM_B ((2*OP_A_H + 2*OP_B_H)*2)   // 87040 B

__global__ __launch_bounds__(256) void oproj_kernel(
    const float* __restrict__ bo, float* __restrict__ out)
{
    extern __shared__ __half smh[];
    __half* As[2] = { smh, smh + OP_A_H };
    __half* Bs[2] = { smh + 2*OP_A_H, smh + 2*OP_A_H + OP_B_H };

    const int M0 = blockIdx.x * 32;
    const int tid = threadIdx.x;
    const int wid = tid >> 5, lane = tid & 31;
    const int warp_m = wid >> 2, warp_n = wid & 3;

    #define CPAB(k, buf) do { \
        uint32_t da_ = (uint32_t)__cvta_generic_to_shared(As[buf]); \
        _Pragma("unroll") \
        for (int i_ = 0; i_ < 2; i_++) { \
            int idx_ = tid + i_*256; \
            int r_ = idx_ >> 4, c_ = idx_ & 15; \
            CP16(da_ + (uint32_t)(r_*136 + c_*8)*2u, \
                 g_att + (size_t)(M0+r_)*HD_ + (k)*128 + c_*8); } \
        uint32_t db_ = (uint32_t)__cvta_generic_to_shared(Bs[buf]); \
        _Pragma("unroll") \
        for (int i_ = 0; i_ < 8; i_++) { \
            int idx_ = tid + i_*256; \
            int r_ = idx_ >> 4, c_ = idx_ & 15; \
            CP16(db_ + (uint32_t)(r_*136 + c_*8)*2u, \
                 g_Wo + (size_t)((k)*128 + r_)*D_ + c_*8); } } while (0)

    CPAB(0, 0); CP_COMMIT();
    CPAB(1, 1); CP_COMMIT();

    wmma::fragment<wmma::accumulator,16,16,16,float> acc[2];
    #pragma unroll
    for (int jn = 0; jn < 2; jn++) wmma::fill_fragment(acc[jn], 0.f);

    #pragma unroll 1
    for (int k = 0; k < 8; k++) {
        CP_WAIT(1);                     // chunk k landed (k+1 in flight)
        __syncthreads();

        const __half* Ak = As[k & 1];
        const __half* Bk = Bs[k & 1];
        #pragma unroll
        for (int kk = 0; kk < 8; kk++) {
            wmma::fragment<wmma::matrix_a,16,16,16,__half,wmma::row_major> af;
            wmma::fragment<wmma::matrix_b,16,16,16,__half,wmma::row_major> bf[2];
            wmma::load_matrix_sync(af, Ak + (warp_m*16)*136 + kk*16, 136);
            #pragma unroll
            for (int jn = 0; jn < 2; jn++)
                wmma::load_matrix_sync(bf[jn], Bk + (kk*16)*136 + warp_n*32 + jn*16, 136);
            #pragma unroll
            for (int jn = 0; jn < 2; jn++)
                wmma::mma_sync(acc[jn], af, bf[jn], acc[jn]);
        }

        __syncthreads();                // buffer k&1 reads done
        if (k + 2 < 8) { CPAB(k+2, k & 1); }
        CP_COMMIT();
    }

    // epilogue: fp32 out + bias (staging ldm 36)
    float* stg = reinterpret_cast<float*>(smh) + wid*(16*36);
    #pragma unroll
    for (int jn = 0; jn < 2; jn++)
        wmma::store_matrix_sync(stg + jn*16, acc[jn], 36, wmma::mem_row_major);
    __syncwarp();
    float bw = bo[warp_n*32 + lane];
    #pragma unroll
    for (int r = 0; r < 16; r++)
        out[(size_t)(M0 + warp_m*16 + r)*D_ + warp_n*32 + lane] = stg[r*36 + lane] + bw;
    #undef CPAB
}

// ---------------------------------------------------------------------------
extern "C" void kernel_launch(void* const* d_in, const int* in_sizes, int n_in,
                              void* d_out, int out_size)
{
    (void)in_sizes; (void)n_in; (void)out_size;
    const float* query = (const float*)d_in[0];
    const float* key   = (const float*)d_in[1];
    const float* value = (const float*)d_in[2];
    const float* pos   = (const float*)d_in[3];
    const int*   mask  = (const int*)  d_in[4];
    const float* Wq = (const float*)d_in[5];
    const float* bq = (const float*)d_in[6];
    const float* Wk = (const float*)d_in[7];
    const float* bk = (const float*)d_in[8];
    const float* Wv = (const float*)d_in[9];
    const float* bv = (const float*)d_in[10];
    const float* Wo = (const float*)d_in[11];
    const float* bo = (const float*)d_in[12];
    float* out = (float*)d_out;

    cudaFuncSetAttribute(proj_kernel,
                         cudaFuncAttributeMaxDynamicSharedMemorySize, PROJ_SMEM_B);
    cudaFuncSetAttribute(attn_kernel,
                         cudaFuncAttributeMaxDynamicSharedMemorySize, ATT_SMEM_B);
    cudaFuncSetAttribute(oproj_kernel,
                         cudaFuncAttributeMaxDynamicSharedMemorySize, OP_SMEM_B);

    prep_kernel<<<dim3(1024, 1, 3), 256>>>(query, key, value, pos, Wq, Wk, Wv, Wo);

    proj_kernel<<<dim3(HD_/128, (B_*S_)/128, 3), 256, PROJ_SMEM_B>>>(bq, bk, bv);

    attn_kernel<<<dim3(S_/64, B_*H_), 128, ATT_SMEM_B>>>(mask);

    oproj_kernel<<<dim3((B_*S_)/32), 256, OP_SMEM_B>>>(bo, out);
}

// round 16
// speedup vs baseline: 1.0714x; 1.0714x over previous
#include <cuda_runtime.h>
#include <cuda_fp16.h>
#include <mma.h>
#include <cstdint>

using namespace nvcuda;

#define B_  8
#define S_  1024
#define D_  128
#define H_  8
#define HD_ 1024

// Scratch (device globals: allocation-free rule)
__device__ __half g_x[3][B_*S_*D_];      // query+pos, key+pos, value+pos (half)
__device__ __half g_W[3][D_*HD_];        // Wq, Wk, Wv (half)
__device__ __half g_Wo[HD_*D_];          // Wo (half)
__device__ __half g_q[B_*H_*S_*D_];      // (b,h,s,d)
__device__ __half g_k[B_*H_*S_*D_];      // (b,h,s,d)
__device__ __half g_vt[B_*H_*D_*S_];     // (b,h,d,s)  V TRANSPOSED
__device__ __half g_att[B_*S_*HD_];      // (b,s,h*D+d)

__device__ __forceinline__ uint32_t pack_h2(float lo, float hi) {
    uint32_t u;
    asm("cvt.rn.f16x2.f32 %0, %2, %1;" : "=r"(u) : "f"(lo), "f"(hi));
    return u;
}

#define MMA_F16(c, a0, a1, a2, a3, b0, b1) \
    asm volatile("mma.sync.aligned.m16n8k16.row.col.f32.f16.f16.f32 " \
        "{%0,%1,%2,%3}, {%4,%5,%6,%7}, {%8,%9}, {%0,%1,%2,%3};" \
        : "+f"((c)[0]), "+f"((c)[1]), "+f"((c)[2]), "+f"((c)[3]) \
        : "r"(a0), "r"(a1), "r"(a2), "r"(a3), "r"(b0), "r"(b1))

#define LDSM_X4(r0, r1, r2, r3, addr) \
    asm volatile("ldmatrix.sync.aligned.m8n8.x4.shared.b16 {%0,%1,%2,%3}, [%4];" \
        : "=r"(r0), "=r"(r1), "=r"(r2), "=r"(r3) : "r"(addr))

#define CP16(smem_u32, gptr) \
    asm volatile("cp.async.cg.shared.global [%0], [%1], 16;" :: "r"(smem_u32), "l"(gptr))
#define CP_COMMIT() asm volatile("cp.async.commit_group;")
#define CP_WAIT(n)  asm volatile("cp.async.wait_group %0;" :: "n"(n))

// ---------------------------------------------------------------------------
// Prep (merged): z = 0..2.  All blocks: x[z] = half(in[z] + pos).
// Blocks 0-127 additionally convert W[z]; z==2 blocks 128-255 convert Wo.
// ---------------------------------------------------------------------------
__global__ __launch_bounds__(256) void prep_kernel(
    const float* __restrict__ query, const float* __restrict__ key,
    const float* __restrict__ value, const float* __restrict__ pos,
    const float* __restrict__ Wq, const float* __restrict__ Wk,
    const float* __restrict__ Wv, const float* __restrict__ Wo)
{
    const int z = blockIdx.z;
    const float* in = (z == 0) ? query : (z == 1 ? key : value);
    int idx = (blockIdx.x*256 + threadIdx.x)*4;
    {
        float4 a = *reinterpret_cast<const float4*>(in + idx);
        float4 p = *reinterpret_cast<const float4*>(pos + idx);
        uint2 o;
        o.x = pack_h2(a.x+p.x, a.y+p.y);
        o.y = pack_h2(a.z+p.z, a.w+p.w);
        *reinterpret_cast<uint2*>(&g_x[z][idx]) = o;
    }
    if (blockIdx.x < 128) {
        const float* W = (z == 0) ? Wq : (z == 1 ? Wk : Wv);
        float4 a = *reinterpret_cast<const float4*>(W + idx);
        uint2 o;
        o.x = pack_h2(a.x, a.y);
        o.y = pack_h2(a.z, a.w);
        *reinterpret_cast<uint2*>(&g_W[z][idx]) = o;
    } else if (z == 2 && blockIdx.x < 256) {
        int widx = idx - 128*256*4;
        float4 a = *reinterpret_cast<const float4*>(Wo + widx);
        uint2 o;
        o.x = pack_h2(a.x, a.y);
        o.y = pack_h2(a.z, a.w);
        *reinterpret_cast<uint2*>(&g_Wo[widx]) = o;
    }
}

// ---------------------------------------------------------------------------
// Kernel 1: projection GEMM (half).  out = x[z](8192x128) @ W[z](128x1024)+bias
// CTA 128x128 tile, pipelined B loads. q/k -> (b,h,s,d); v -> (b,h,d,s).
// ---------------------------------------------------------------------------
#define PROJ_A_H    (128*136)                 // 17408 halves
#define PROJ_B_H    (64*136)                  // 8704 halves
#define PROJ_STG_F  (64*36)                   // fp32 staging floats per warp
#define PROJ_SMEM_B 73728

__global__ __launch_bounds__(256) void proj_kernel(
    const float* __restrict__ bq, const float* __restrict__ bk,
    const float* __restrict__ bv)
{
    extern __shared__ __half smh[];
    __half* As = smh;
    __half* Bs[2] = { smh + PROJ_A_H, smh + PROJ_A_H + PROJ_B_H };

    const int which = blockIdx.z;
    const float* bias = (which == 0) ? bq : (which == 1 ? bk : bv);

    const int M0 = blockIdx.y * 128;
    const int N0 = blockIdx.x * 128;
    const int tid = threadIdx.x;
    const int wid = tid >> 5, lane = tid & 31;
    const int warp_m = wid >> 2, warp_n = wid & 3;

    const uint32_t da = (uint32_t)__cvta_generic_to_shared(As);
    const __half* Ag = g_x[which] + (size_t)M0*D_;
    const __half* Bg = g_W[which] + N0;

    // group0: full A (128x128) + B chunk 0 (rows 0-63)
    #pragma unroll
    for (int i = 0; i < 8; i++) {
        int idx = tid + i*256;
        int r = idx >> 4, c = idx & 15;
        CP16(da + (uint32_t)(r*136 + c*8)*2u, Ag + (size_t)r*D_ + c*8);
    }
    {
        uint32_t db = (uint32_t)__cvta_generic_to_shared(Bs[0]);
        #pragma unroll
        for (int i = 0; i < 4; i++) {
            int idx = tid + i*256;
            int r = idx >> 4, c = idx & 15;
            CP16(db + (uint32_t)(r*136 + c*8)*2u, Bg + (size_t)r*HD_ + c*8);
        }
    }
    CP_COMMIT();
    // group1: B chunk 1 (rows 64-127)
    {
        uint32_t db = (uint32_t)__cvta_generic_to_shared(Bs[1]);
        #pragma unroll
        for (int i = 0; i < 4; i++) {
            int idx = tid + i*256;
            int r = idx >> 4, c = idx & 15;
            CP16(db + (uint32_t)(r*136 + c*8)*2u, Bg + (size_t)(64 + r)*HD_ + c*8);
        }
    }
    CP_COMMIT();

    wmma::fragment<wmma::accumulator,16,16,16,float> acc[4][2];
    #pragma unroll
    for (int im = 0; im < 4; im++)
        #pragma unroll
        for (int jn = 0; jn < 2; jn++)
            wmma::fill_fragment(acc[im][jn], 0.f);

    #pragma unroll
    for (int ch = 0; ch < 2; ch++) {
        if (ch == 0) CP_WAIT(1); else CP_WAIT(0);
        __syncthreads();
        const __half* Bsk = Bs[ch];
        #pragma unroll
        for (int kk = 0; kk < 4; kk++) {
            wmma::fragment<wmma::matrix_a,16,16,16,__half,wmma::row_major> af[4];
            wmma::fragment<wmma::matrix_b,16,16,16,__half,wmma::row_major> bf[2];
            #pragma unroll
            for (int im = 0; im < 4; im++)
                wmma::load_matrix_sync(af[im],
                    As + (warp_m*64 + im*16)*136 + ch*64 + kk*16, 136);
            #pragma unroll
            for (int jn = 0; jn < 2; jn++)
                wmma::load_matrix_sync(bf[jn], Bsk + (kk*16)*136 + warp_n*32 + jn*16, 136);
            #pragma unroll
            for (int im = 0; im < 4; im++)
                #pragma unroll
                for (int jn = 0; jn < 2; jn++)
                    wmma::mma_sync(acc[im][jn], af[im], bf[jn], acc[im][jn]);
        }
    }
    __syncthreads();   // smem free for fp32 staging

    float* stg = reinterpret_cast<float*>(smh) + wid*PROJ_STG_F;
    #pragma unroll
    for (int im = 0; im < 4; im++)
        #pragma unroll
        for (int jn = 0; jn < 2; jn++)
            wmma::store_matrix_sync(stg + (im*16)*36 + jn*16, acc[im][jn], 36,
                                    wmma::mem_row_major);
    __syncwarp();

    const int b = M0 >> 10;
    const int h = N0 >> 7;

    if (which < 2) {
        __half* outp = (which == 0) ? g_q : g_k;
        #pragma unroll
        for (int it = 0; it < 8; it++) {
            int r = it*8 + (lane >> 2);
            int c0 = (lane & 3)*8;
            int gm = M0 + warp_m*64 + r;
            int s = gm & 1023;
            int d0 = warp_n*32 + c0;
            uint32_t v[4];
            #pragma unroll
            for (int e = 0; e < 4; e++)
                v[e] = pack_h2(stg[r*36 + c0 + 2*e]     + bias[N0 + d0 + 2*e],
                               stg[r*36 + c0 + 2*e + 1] + bias[N0 + d0 + 2*e + 1]);
            *reinterpret_cast<uint4*>(outp + (((size_t)b*H_ + h)*S_ + s)*D_ + d0) =
                *reinterpret_cast<uint4*>(v);
        }
    } else {
        // v: write transposed (b,h,d,s). lane = d-col of warp subtile.
        int d = warp_n*32 + lane;
        float bv_ = bias[N0 + d];
        int s0 = (M0 & 1023) + warp_m*64;
        #pragma unroll
        for (int sp = 0; sp < 8; sp++) {
            uint32_t v[4];
            #pragma unroll
            for (int e = 0; e < 4; e++)
                v[e] = pack_h2(stg[(sp*8 + 2*e)*36 + lane]     + bv_,
                               stg[(sp*8 + 2*e + 1)*36 + lane] + bv_);
            *reinterpret_cast<uint4*>(
                g_vt + (((size_t)b*H_ + h)*D_ + d)*S_ + s0 + sp*8) =
                *reinterpret_cast<uint4*>(v);
        }
    }
}

// ---------------------------------------------------------------------------
// Kernel 2: flash attention. fp16 mma m16n8k16, single-pass softmax (2^-8
// offset), ldmatrix.x4 B-frags, K/Vt double-buffered, 3 CTAs/SM, l via
// ones-mma, direct-store epilogue. (round-11 measured optimum)
// ---------------------------------------------------------------------------
#define ATT_K_H     (64*136)     // 8704 halves
#define ATT_V_H     (128*72)     // 9216 halves
#define ATT_SMEM_B  ((2*ATT_K_H + 2*ATT_V_H)*2 + 256)

__device__ __forceinline__ void cp_ktile(__half* dst, const __half* src, int tid) {
    uint32_t d = (uint32_t)__cvta_generic_to_shared(dst);
    #pragma unroll
    for (int i = 0; i < 8; i++) {
        int idx = tid + i*128;
        int r = idx >> 4, c = idx & 15;
        CP16(d + (uint32_t)(r*136 + c*8)*2u, src + (size_t)r*D_ + c*8);
    }
}
__device__ __forceinline__ void cp_vtile(__half* dst, const __half* src, int tid) {
    uint32_t d = (uint32_t)__cvta_generic_to_shared(dst);
    #pragma unroll
    for (int i = 0; i < 8; i++) {
        int idx = tid + i*128;
        int r = idx >> 3, c = idx & 7;
        CP16(d + (uint32_t)(r*72 + c*8)*2u, src + (size_t)r*S_ + c*8);
    }
}

__global__ __launch_bounds__(128, 3) void attn_kernel(const int* __restrict__ mask)
{
    extern __shared__ __half smh[];
    __half* Ks[2] = { smh, smh + ATT_K_H };
    __half* Vs[2] = { smh + 2*ATT_K_H, smh + 2*ATT_K_H + ATT_V_H };
    float* mbias  = reinterpret_cast<float*>(smh + 2*ATT_K_H + 2*ATT_V_H);

    const int q0 = blockIdx.x * 64;
    const int bh = blockIdx.y;
    const int b  = bh >> 3;
    const int tid = threadIdx.x;
    const int wid = tid >> 5, lane = tid & 31;
    const int g = lane >> 2, t = lane & 3;

    // ldmatrix lane roles
    const int rl   = lane & 7;
    const int msel = (lane >> 3) & 1;
    const int jh   = lane >> 4;

    const uint32_t sbase = (uint32_t)__cvta_generic_to_shared(smh);
    const uint32_t koff = (uint32_t)(((jh*8 + rl)*136 + msel*8)*2);
    const uint32_t voff = (uint32_t)(((jh*8 + rl)*72  + msel*8)*2);

    const __half* Qg = g_q  + ((size_t)bh*S_ + q0)*D_;
    const __half* Kg = g_k  + (size_t)bh*S_*D_;
    const __half* Vg = g_vt + (size_t)bh*D_*S_;

    // G0: K0 -> Ks[0]; G1: Q -> Ks[1] (staging); G2: V0 -> Vs[0]
    cp_ktile(Ks[0], Kg, tid);   CP_COMMIT();
    cp_ktile(Ks[1], Qg, tid);   CP_COMMIT();
    cp_vtile(Vs[0], Vg, tid);   CP_COMMIT();
    CP_WAIT(1);                 // K0, Q landed
    __syncthreads();

    // Q fragments: 8 k16-chunks x 4 regs
    uint32_t qa[8][4];
    {
        const __half* Qw = Ks[1] + (16*wid)*136;
        #pragma unroll
        for (int kc = 0; kc < 8; kc++) {
            qa[kc][0] = *reinterpret_cast<const uint32_t*>(Qw + (g    )*136 + kc*16 + 2*t);
            qa[kc][1] = *reinterpret_cast<const uint32_t*>(Qw + (g + 8)*136 + kc*16 + 2*t);
            qa[kc][2] = *reinterpret_cast<const uint32_t*>(Qw + (g    )*136 + kc*16 + 2*t + 8);
            qa[kc][3] = *reinterpret_cast<const uint32_t*>(Qw + (g + 8)*136 + kc*16 + 2*t + 8);
        }
    }
    __syncthreads();   // all warps read Q -> Ks[1] free

    // G3: K1 -> Ks[1]; G4: V1 -> Vs[1]
    cp_ktile(Ks[1], Kg + 64*D_, tid);  CP_COMMIT();
    cp_vtile(Vs[1], Vg + 64,    tid);  CP_COMMIT();

    float oacc[16][4];
    #pragma unroll
    for (int j = 0; j < 16; j++)
        #pragma unroll
        for (int e = 0; e < 4; e++) oacc[j][e] = 0.f;
    float lacc[4] = {0.f, 0.f, 0.f, 0.f};      // l via ones-mma: c0=row g, c2=row g+8
    const uint32_t ONES = 0x3C003C00u;          // fp16x2 {1.0, 1.0}
    const float scale = 0.08838834764831845f;   // 1/sqrt(128)
    const float EOFF  = 5.545177444479562f;     // 8*ln2: P scaled by 2^-8

    #pragma unroll 1
    for (int kt = 0; kt < 16; kt++) {
        if (tid < 64) mbias[tid] = (mask[b*S_ + kt*64 + tid] ? 0.f : -1e30f) - EOFF;
        CP_WAIT(2);                 // K[kt], V[kt] ready; [kt+1] in flight
        __syncthreads();

        // ---- S = Q K^T : 16 rows x 64 cols per warp (ldmatrix B-frags) ----
        float sacc[8][4];
        #pragma unroll
        for (int j = 0; j < 8; j++)
            #pragma unroll
            for (int e = 0; e < 4; e++) sacc[j][e] = 0.f;

        const uint32_t sKb = sbase + (uint32_t)(kt & 1)*ATT_K_H*2 + koff;
        #pragma unroll
        for (int kc = 0; kc < 8; kc++) {
            #pragma unroll
            for (int q = 0; q < 4; q++) {
                uint32_t b0a, b1a, b0b, b1b;
                LDSM_X4(b0a, b1a, b0b, b1b,
                        sKb + (uint32_t)((q*16*136 + kc*16)*2));
                MMA_F16(sacc[2*q],     qa[kc][0], qa[kc][1], qa[kc][2], qa[kc][3], b0a, b1a);
                MMA_F16(sacc[2*q + 1], qa[kc][0], qa[kc][1], qa[kc][2], qa[kc][3], b0b, b1b);
            }
        }

        // ---- single-pass softmax (2^-8 offset) -> fp16 P frags ----
        uint32_t pa[4][4];
        #pragma unroll
        for (int j = 0; j < 8; j++) {
            float bj0 = mbias[8*j + 2*t], bj1 = mbias[8*j + 2*t + 1];
            float p0 = __expf(fmaf(sacc[j][0], scale, bj0));
            float p1 = __expf(fmaf(sacc[j][1], scale, bj1));
            float p2 = __expf(fmaf(sacc[j][2], scale, bj0));
            float p3 = __expf(fmaf(sacc[j][3], scale, bj1));
            int kc = j >> 1, hi = j & 1;
            pa[kc][0 + 2*hi] = pack_h2(p0, p1);   // row g
            pa[kc][1 + 2*hi] = pack_h2(p2, p3);   // row g+8
        }

        // ---- l += P @ ones (exact fp32 row-sums of rounded P) ----
        #pragma unroll
        for (int kc = 0; kc < 4; kc++)
            MMA_F16(lacc, pa[kc][0], pa[kc][1], pa[kc][2], pa[kc][3], ONES, ONES);

        // ---- O += P V (ldmatrix B-frags from Vt) ----
        const uint32_t sVb = sbase + (uint32_t)(2*ATT_K_H + (kt & 1)*ATT_V_H)*2 + voff;
        #pragma unroll
        for (int kc = 0; kc < 4; kc++) {
            #pragma unroll
            for (int q = 0; q < 8; q++) {
                uint32_t b0a, b1a, b0b, b1b;
                LDSM_X4(b0a, b1a, b0b, b1b,
                        sVb + (uint32_t)((q*16*72 + kc*16)*2));
                MMA_F16(oacc[2*q],     pa[kc][0], pa[kc][1], pa[kc][2], pa[kc][3], b0a, b1a);
                MMA_F16(oacc[2*q + 1], pa[kc][0], pa[kc][1], pa[kc][2], pa[kc][3], b0b, b1b);
            }
        }

        __syncthreads();           // tile reads done -> buffers reusable
        if (kt + 2 < 16) {
            cp_ktile(Ks[kt & 1], Kg + (size_t)(kt+2)*64*D_, tid);
            CP_COMMIT();
            cp_vtile(Vs[kt & 1], Vg + (kt+2)*64, tid);
            CP_COMMIT();
        } else { CP_COMMIT(); CP_COMMIT(); }   // keep group accounting
    }

    // ---- finalize: O/l -> g_att (half). l = lacc (no shuffles needed). ----
    {
        float inv0 = 1.f / lacc[0], inv8 = 1.f / lacc[2];
        int h = bh & 7;
        int row0 = q0 + 16*wid + g;
        __half* Ob = g_att + ((size_t)(b*S_ + row0))*HD_ + h*D_;
        #pragma unroll
        for (int j = 0; j < 16; j++) {
            int col = 8*j + 2*t;
            *reinterpret_cast<uint32_t*>(Ob + col) =
                pack_h2(oacc[j][0]*inv0, oacc[j][1]*inv0);
            *reinterpret_cast<uint32_t*>(Ob + (size_t)8*HD_ + col) =
                pack_h2(oacc[j][2]*inv8, oacc[j][3]*inv8);
        }
    }
}

// ---------------------------------------------------------------------------
// Kernel 3: output projection. CTA 32x128, 3-stage cp.async, trailing
// per-iter barrier elided (3-deep ring ordering). (round-11 measured optimum)
// ---------------------------------------------------------------------------
#define OP_A_H    (32*72)
#define OP_B_H    (64*136)
#define OP_SMEM_B ((3*OP_A_H + 3*OP_B_H)*2)

__global__ __launch_bounds__(256) void oproj_kernel(
    const float* __restrict__ bo, float* __restrict__ out)
{
    extern __shared__ __half smh[];
    __half* As[3] = { smh, smh + OP_A_H, smh + 2*OP_A_H };
    __half* Bs[3] = { smh + 3*OP_A_H, smh + 3*OP_A_H + OP_B_H,
                      smh + 3*OP_A_H + 2*OP_B_H };

    const int M0 = blockIdx.x * 32;
    const int tid = threadIdx.x;
    const int wid = tid >> 5, lane = tid & 31;
    const int warp_m = wid >> 2, warp_n = wid & 3;

    #define CPAB(k, buf) do { \
        uint32_t da_ = (uint32_t)__cvta_generic_to_shared(As[buf]); \
        { int r_ = tid >> 3, c_ = tid & 7; \
          CP16(da_ + (uint32_t)(r_*72 + c_*8)*2u, \
               g_att + (size_t)(M0+r_)*HD_ + (k)*64 + c_*8); } \
        uint32_t db_ = (uint32_t)__cvta_generic_to_shared(Bs[buf]); \
        _Pragma("unroll") \
        for (int i_ = 0; i_ < 4; i_++) { \
            int idx_ = tid + i_*256; \
            int r_ = idx_ >> 4, c_ = idx_ & 15; \
            CP16(db_ + (uint32_t)(r_*136 + c_*8)*2u, \
                 g_Wo + (size_t)((k)*64 + r_)*D_ + c_*8); } } while (0)

    CPAB(0, 0); CP_COMMIT();
    CPAB(1, 1); CP_COMMIT();

    wmma::fragment<wmma::accumulator,16,16,16,float> acc[2];
    #pragma unroll
    for (int jn = 0; jn < 2; jn++) wmma::fill_fragment(acc[jn], 0.f);

    #pragma unroll 1
    for (int k = 0; k < 16; k++) {
        CP_WAIT(1);
        __syncthreads();
        if (k + 2 < 16) { CPAB(k+2, (k+2) % 3); }
        CP_COMMIT();

        const __half* Ak = As[k % 3];
        const __half* Bk = Bs[k % 3];
        #pragma unroll
        for (int kk = 0; kk < 4; kk++) {
            wmma::fragment<wmma::matrix_a,16,16,16,__half,wmma::row_major> af;
            wmma::fragment<wmma::matrix_b,16,16,16,__half,wmma::row_major> bf[2];
            wmma::load_matrix_sync(af, Ak + (warp_m*16)*72 + kk*16, 72);
            #pragma unroll
            for (int jn = 0; jn < 2; jn++)
                wmma::load_matrix_sync(bf[jn], Bk + (kk*16)*136 + warp_n*32 + jn*16, 136);
            #pragma unroll
            for (int jn = 0; jn < 2; jn++)
                wmma::mma_sync(acc[jn], af, bf[jn], acc[jn]);
        }
    }
    __syncthreads();   // all tile reads done before staging overwrite

    float* stg = reinterpret_cast<float*>(smh) + wid*(16*36);
    #pragma unroll
    for (int jn = 0; jn < 2; jn++)
        wmma::store_matrix_sync(stg + jn*16, acc[jn], 36, wmma::mem_row_major);
    __syncwarp();
    float bw = bo[warp_n*32 + lane];
    #pragma unroll
    for (int r = 0; r < 16; r++)
        out[(size_t)(M0 + warp_m*16 + r)*D_ + warp_n*32 + lane] = stg[r*36 + lane] + bw;
    #undef CPAB
}

// ---------------------------------------------------------------------------
extern "C" void kernel_launch(void* const* d_in, const int* in_sizes, int n_in,
                              void* d_out, int out_size)
{
    (void)in_sizes; (void)n_in; (void)out_size;
    const float* query = (const float*)d_in[0];
    const float* key   = (const float*)d_in[1];
    const float* value = (const float*)d_in[2];
    const float* pos   = (const float*)d_in[3];
    const int*   mask  = (const int*)  d_in[4];
    const float* Wq = (const float*)d_in[5];
    const float* bq = (const float*)d_in[6];
    const float* Wk = (const float*)d_in[7];
    const float* bk = (const float*)d_in[8];
    const float* Wv = (const float*)d_in[9];
    const float* bv = (const float*)d_in[10];
    const float* Wo = (const float*)d_in[11];
    const float* bo = (const float*)d_in[12];
    float* out = (float*)d_out;

    cudaFuncSetAttribute(proj_kernel,
                         cudaFuncAttributeMaxDynamicSharedMemorySize, PROJ_SMEM_B);
    cudaFuncSetAttribute(attn_kernel,
                         cudaFuncAttributeMaxDynamicSharedMemorySize, ATT_SMEM_B);
    cudaFuncSetAttribute(oproj_kernel,
                         cudaFuncAttributeMaxDynamicSharedMemorySize, OP_SMEM_B);

    prep_kernel<<<dim3(1024, 1, 3), 256>>>(query, key, value, pos, Wq, Wk, Wv, Wo);

    proj_kernel<<<dim3(HD_/128, (B_*S_)/128, 3), 256, PROJ_SMEM_B>>>(bq, bk, bv);

    attn_kernel<<<dim3(S_/64, B_*H_), 128, ATT_SMEM_B>>>(mask);

    oproj_kernel<<<dim3((B_*S_)/32), 256, OP_SMEM_B>>>(bo, out);
}